// round 7
// baseline (speedup 1.0000x reference)
#include <cuda_runtime.h>
#include <cuda_fp16.h>
#include <cstdint>

#define NB 4096
#define NT 32               // 32x32 grid of 128x128 tiles
#define NITEMS 1056         // two 128x64 half-tiles per upper-triangle tile

// ---------------- device scratch (static: no allocation allowed) ----------------
// C row (256 fp16): [x | -2m | 1/v | m/v], x = v + m^2
// "D" row = C rotated by 128 cols; chunk q of D = chunk q^2 of C (64-col chunks).
__device__ __half g_C[(size_t)NB * 256];
__device__ float  g_A8[NB];    // 0.125*a_i - 8
__device__ float  g_P8[NB];    // 0.125*p_i
__device__ float  g_Q[NB];     // 1/(p_i + 1e-8)
__device__ double g_pos, g_neg;
// persistent-kernel coordination (self-resetting across graph replays)
__device__ unsigned g_arrive = 0, g_done = 0, g_ticket = 0;
__device__ volatile unsigned g_release = 0;

static __device__ __forceinline__ uint32_t smem_u32(const void* p) {
    uint32_t a;
    asm("{ .reg .u64 t; cvta.to.shared.u64 t, %1; cvt.u32.u64 %0, t; }" : "=r"(a) : "l"(p));
    return a;
}
static __device__ __forceinline__ float frcp(float x) {
    float r; asm("rcp.approx.f32 %0, %1;" : "=f"(r) : "f"(x)); return r;
}
static __device__ __forceinline__ float ftanh(float x) {
    float r; asm("tanh.approx.f32 %0, %1;" : "=f"(r) : "f"(x)); return r;
}
static __device__ __forceinline__ void cpa16(uint32_t dst, const void* src) {
    asm volatile("cp.async.ca.shared.global [%0], [%1], 16;" :: "r"(dst), "l"(src));
}
static __device__ __forceinline__ void cpa4(uint32_t dst, const void* src) {
    asm volatile("cp.async.ca.shared.global [%0], [%1], 4;" :: "r"(dst), "l"(src));
}
static __device__ __forceinline__ void cp_commit() {
    asm volatile("cp.async.commit_group;" ::: "memory");
}
static __device__ __forceinline__ void cp_wait1() {
    asm volatile("cp.async.wait_group 1;" ::: "memory");
}

// smem: 2 x (A chunk 128x64fp16 + B chunk 64x64fp16, XOR-swizzled, pitch 128B)
//       + 2 x params + reduce scratch
#define BUF_STRIDE 24576               // A 16384 + B 8192
#define BUFA(b) ((b) * BUF_STRIDE)
#define BUFB(b) ((b) * BUF_STRIDE + 16384)
#define PAR_OFF 49152                  // 2 x 3072
#define PAR_SZ  3072
#define RED_OFF (PAR_OFF + 2 * PAR_SZ) // 55296
#define SMEM_BYTES (RED_OFF + 64)      // 55360

// ---- stage one 64-wide K chunk: A rows [Ibase,+128), B rows [Jbase,+64) ----
static __device__ __forceinline__ void stage_chunk(
    uint32_t sbase, int buf, const char* baseI, const char* baseJ, int q, int tid)
{
    int qa = q * 128, qb = (q ^ 2) * 128;
    #pragma unroll
    for (int p = 0; p < 8; p++) {
        int s = tid + p * 128, row = s >> 3, c16 = s & 7;
        uint32_t dst = sbase + BUFA(buf) + row * 128 + (((c16 ^ (row & 7))) << 4);
        cpa16(dst, baseI + row * 512 + qa + c16 * 16);
    }
    #pragma unroll
    for (int p = 0; p < 4; p++) {
        int s = tid + p * 128, row = s >> 3, c16 = s & 7;
        uint32_t dst = sbase + BUFB(buf) + row * 128 + (((c16 ^ (row & 7))) << 4);
        cpa16(dst, baseJ + row * 512 + qb + c16 * 16);
    }
}
// ---- stage per-row params for an item into parity buffer ----
static __device__ __forceinline__ void stage_params(
    uint32_t pbase, const int* labels, int Ibase, int Jbase, int tid)
{
    if (tid < 128) {
        cpa4(pbase +        tid * 4, g_A8 + Ibase + tid);
        cpa4(pbase + 512  + tid * 4, g_P8 + Ibase + tid);
        cpa4(pbase + 1024 + tid * 4, g_Q  + Ibase + tid);
        cpa4(pbase + 1536 + tid * 4, labels + Ibase + tid);
        if (tid < 64) {
            cpa4(pbase + 2048 + tid * 4, g_A8 + Jbase + tid);
            cpa4(pbase + 2304 + tid * 4, g_P8 + Jbase + tid);
            cpa4(pbase + 2560 + tid * 4, g_Q  + Jbase + tid);
            cpa4(pbase + 2816 + tid * 4, labels + Jbase + tid);
        }
    }
}

// ---- one 64-wide K chunk of the 128x64 GEMM (warp tile 64x32) ----
static __device__ __forceinline__ void gemm_chunk(
    uint32_t bufA, uint32_t bufB, int lane, int warp_m, int warp_n,
    uint32_t (&h)[4][4][2])
{
    #pragma unroll
    for (int k0 = 0; k0 < 64; k0 += 16) {
        uint32_t af[4][4];
        #pragma unroll
        for (int mi = 0; mi < 4; mi++) {
            int r = warp_m * 64 + mi * 16 + (lane & 15);
            int c16 = (k0 >> 3) + (lane >> 4);
            uint32_t addr = bufA + r * 128 + ((c16 ^ (r & 7)) << 4);
            asm volatile("ldmatrix.sync.aligned.m8n8.x4.shared.b16 {%0,%1,%2,%3}, [%4];"
                         : "=r"(af[mi][0]), "=r"(af[mi][1]), "=r"(af[mi][2]), "=r"(af[mi][3])
                         : "r"(addr));
        }
        #pragma unroll
        for (int ni = 0; ni < 4; ni++) {
            int r = warp_n * 32 + ni * 8 + (lane & 7);
            int c16 = (k0 >> 3) + ((lane >> 3) & 1);
            uint32_t addr = bufB + r * 128 + ((c16 ^ (r & 7)) << 4);
            uint32_t b0, b1;
            asm volatile("ldmatrix.sync.aligned.m8n8.x2.shared.b16 {%0,%1}, [%2];"
                         : "=r"(b0), "=r"(b1) : "r"(addr));
            #pragma unroll
            for (int mi = 0; mi < 4; mi++) {
                asm volatile(
                    "mma.sync.aligned.m16n8k16.row.col.f16.f16.f16.f16 "
                    "{%0,%1}, {%2,%3,%4,%5}, {%6,%7}, {%0,%1};"
                    : "+r"(h[mi][ni][0]), "+r"(h[mi][ni][1])
                    : "r"(af[mi][0]), "r"(af[mi][1]), "r"(af[mi][2]), "r"(af[mi][3]),
                      "r"(b0), "r"(b1));
            }
        }
    }
}

static __device__ __forceinline__ void decode_item(unsigned t, int& I, int& J, int& half) {
    int ft = (int)(t >> 1); half = (int)(t & 1); I = 0;
    while (ft >= NT - I) { ft -= NT - I; I++; }
    J = I + ft;
}

__global__ void __launch_bounds__(128, 4) mega_kernel(
    const float* __restrict__ mu, const float* __restrict__ var,
    const int* __restrict__ labels, float* __restrict__ out)
{
    extern __shared__ char smem[];
    uint32_t sbase = smem_u32(smem);
    int tid = threadIdx.x, lane = tid & 31, wid = tid >> 5;

    // ================= phase 0: prep (8 rows per CTA pass, 16 lanes/row) =================
    for (int row0 = blockIdx.x * 8; row0 < NB; row0 += gridDim.x * 8) {
        int row = row0 + (tid >> 4), l16 = tid & 15;
        float4 m4 = ((const float4*)(mu  + (size_t)row * 64))[l16];
        float4 v4 = ((const float4*)(var + (size_t)row * 64))[l16];
        float m[4] = {m4.x, m4.y, m4.z, m4.w};
        float v[4] = {v4.x, v4.y, v4.z, v4.w};
        float x[4], n2m[4], iv[4], w[4];
        float pv = 1.0f, av = 0.0f;
        #pragma unroll
        for (int d = 0; d < 4; d++) {
            iv[d]  = frcp(v[d]);
            x[d]   = v[d] + m[d] * m[d];
            n2m[d] = -2.0f * m[d];
            w[d]   = m[d] * iv[d];
            pv *= v[d];
            av = fmaf(m[d] * m[d], iv[d], av);
        }
        uint2* crow = (uint2*)(g_C + (size_t)row * 256);
        const float* blocks[4] = {x, n2m, iv, w};
        #pragma unroll
        for (int b = 0; b < 4; b++) {
            const float* s = blocks[b];
            __half2 h2[2] = {__floats2half2_rn(s[0], s[1]), __floats2half2_rn(s[2], s[3])};
            crow[b * 16 + l16] = *(uint2*)h2;
        }
        #pragma unroll
        for (int off = 1; off < 16; off <<= 1) {
            pv *= __shfl_xor_sync(0xffffffffu, pv, off);
            av += __shfl_xor_sync(0xffffffffu, av, off);
        }
        if (l16 == 0) {
            g_A8[row] = 0.125f * av - 8.0f;
            g_P8[row] = 0.125f * pv;
            g_Q[row]  = frcp(pv + 1e-8f);
        }
    }

    // ================= device-wide barrier (all CTAs resident by construction) =================
    __syncthreads();
    if (tid == 0) {
        unsigned target = g_release + 1;
        __threadfence();
        unsigned a = atomicAdd(&g_arrive, 1);
        if (a == gridDim.x - 1) {
            g_arrive = 0;
            g_pos = 0.0; g_neg = 0.0;
            g_ticket = gridDim.x;
            __threadfence();
            atomicAdd((unsigned*)&g_release, 1);
        } else {
            while (g_release < target) __nanosleep(64);
        }
        __threadfence();
    }
    __syncthreads();

    // ================= phase 1: pipelined half-tile loop =================
    float* red = (float*)(smem + RED_OFF);
    unsigned* tick_s = (unsigned*)(red + 8);
    int warp_m = wid & 1, warp_n = wid >> 1;
    float pos = 0.0f, neg = 0.0f;

    unsigned cur = blockIdx.x;
    int ip = 0;
    int I, J, half;
    const char *baseI = nullptr, *baseJ = nullptr;

    if (cur < NITEMS) {
        decode_item(cur, I, J, half);
        baseI = (const char*)g_C + (size_t)I * 128 * 512;
        baseJ = (const char*)g_C + ((size_t)J * 128 + half * 64) * 512;
        // prologue: chunk0 + params -> group0, chunk1 -> group1
        stage_chunk(sbase, 0, baseI, baseJ, 0, tid);
        stage_params(sbase + PAR_OFF, labels, I * 128, J * 128 + half * 64, tid);
        cp_commit();
        stage_chunk(sbase, 1, baseI, baseJ, 1, tid);
        cp_commit();
    }

    while (cur < NITEMS) {
        unsigned nt = 0;
        int nI = 0, nJ = 0, nhalf = 0;
        const char *nbI = nullptr, *nbJ = nullptr;

        uint32_t h[4][4][2];
        #pragma unroll
        for (int mi = 0; mi < 4; mi++)
            #pragma unroll
            for (int ni = 0; ni < 4; ni++) { h[mi][ni][0] = 0u; h[mi][ni][1] = 0u; }

        #pragma unroll
        for (int c = 0; c < 4; c++) {
            cp_wait1();
            __syncthreads();                 // chunk c landed, buffer c&1 readable
            gemm_chunk(sbase + BUFA(c & 1), sbase + BUFB(c & 1),
                       lane, warp_m, warp_n, h);
            __syncthreads();                 // all warps done reading buffer c&1
            if (c == 0) {
                if (tid == 0) *tick_s = atomicAdd(&g_ticket, 1);
                stage_chunk(sbase, 0, baseI, baseJ, 2, tid);
            } else if (c == 1) {
                stage_chunk(sbase, 1, baseI, baseJ, 3, tid);
            } else {
                if (c == 2) {
                    nt = *tick_s;            // written at c=0, syncs in between
                    if (nt < NITEMS) {
                        decode_item(nt, nI, nJ, nhalf);
                        nbI = (const char*)g_C + (size_t)nI * 128 * 512;
                        nbJ = (const char*)g_C + ((size_t)nJ * 128 + nhalf * 64) * 512;
                        stage_chunk(sbase, 0, nbI, nbJ, 0, tid);
                        stage_params(sbase + PAR_OFF + (ip ^ 1) * PAR_SZ, labels,
                                     nI * 128, nJ * 128 + nhalf * 64, tid);
                    }
                } else if (nt < NITEMS) {
                    stage_chunk(sbase, 1, nbI, nbJ, 1, tid);
                }
            }
            cp_commit();                     // always commit to keep wait_group ladder aligned
        }

        // fused epilogue on registers; params from parity buffer ip
        {
            uint32_t pb = sbase + PAR_OFF + ip * PAR_SZ;
            float* spAI = (float*)(smem + (pb - sbase));
            float* spPI = spAI + 128;
            float* spQI = spPI + 128;
            int*   spLI = (int*)(spQI + 128);
            float* spAJ = (float*)(spLI + 128);
            float* spPJ = spAJ + 64;
            float* spQJ = spPJ + 64;
            int*   spLJ = (int*)(spQJ + 64);
            const bool diag = (I == J);
            #pragma unroll
            for (int mi = 0; mi < 4; mi++) {
                #pragma unroll
                for (int k = 0; k < 2; k++) {
                    int r = warp_m * 64 + mi * 16 + (lane >> 2) + k * 8;
                    float RA = spAI[r], RP = spPI[r], RQ = spQI[r];
                    int   RL = spLI[r];
                    #pragma unroll
                    for (int ni = 0; ni < 4; ni++) {
                        __half2 hv = *reinterpret_cast<__half2*>(&h[mi][ni][k]);
                        float2 f = __half22float2(hv);
                        int c0 = warp_n * 32 + ni * 8 + (lane & 3) * 2;
                        #pragma unroll
                        for (int e = 0; e < 2; e++) {
                            int c = c0 + e;
                            float vv = e ? f.y : f.x;
                            float s = fmaf(vv, 0.125f, RA);
                            s += spAJ[c];
                            s = fmaf(RP, spQJ[c], s);
                            s = fmaf(spPJ[c], RQ, s);
                            float sg = fmaf(ftanh(s), 0.5f, 0.5f);
                            bool count = (!diag) || (half * 64 + c > r);
                            bool same  = (RL == spLJ[c]);
                            if (count) {
                                pos += same ? sg : 0.0f;
                                neg += same ? 0.0f : sg;
                            }
                        }
                    }
                }
            }
        }

        cur = nt; I = nI; J = nJ; half = nhalf; baseI = nbI; baseJ = nbJ;
        ip ^= 1;
        __syncthreads();   // params[old ip] free for reuse two items later
    }

    // ================= final reduce + output by last CTA =================
    #pragma unroll
    for (int off = 16; off; off >>= 1) {
        pos += __shfl_xor_sync(0xffffffffu, pos, off);
        neg += __shfl_xor_sync(0xffffffffu, neg, off);
    }
    __syncthreads();
    if (lane == 0) { red[wid] = pos; red[4 + wid] = neg; }
    __syncthreads();
    if (tid == 0) {
        double P = 0.0, Nn = 0.0;
        #pragma unroll
        for (int w = 0; w < 4; w++) { P += (double)red[w]; Nn += (double)red[4 + w]; }
        atomicAdd(&g_pos, P);
        atomicAdd(&g_neg, Nn);
        __threadfence();
        unsigned d = atomicAdd(&g_done, 1);
        if (d == gridDim.x - 1) {
            double TP = 2.0 * atomicAdd(&g_pos, 0.0);
            double TN = 2.0 * atomicAdd(&g_neg, 0.0);
            const double inv = 1.0 / ((double)NB * (double)NB);
            out[0] = (float)(TP * inv);
            out[1] = (float)(TN * inv);
            out[2] = (float)TP;
            out[3] = (float)TN;
            g_done = 0;
        }
    }
}

// ---------------- launcher ----------------
extern "C" void kernel_launch(void* const* d_in, const int* in_sizes, int n_in,
                              void* d_out, int out_size) {
    (void)in_sizes; (void)n_in; (void)out_size;
    const float* mu     = (const float*)d_in[0];
    const float* var    = (const float*)d_in[1];
    const int*   labels = (const int*)d_in[2];
    float* out = (float*)d_out;

    cudaFuncSetAttribute(mega_kernel, cudaFuncAttributeMaxDynamicSharedMemorySize,
                         SMEM_BYTES);
    int occ = 0, sms = 0, dev = 0;
    cudaGetDevice(&dev);
    cudaOccupancyMaxActiveBlocksPerMultiprocessor(&occ, mega_kernel, 128, SMEM_BYTES);
    cudaDeviceGetAttribute(&sms, cudaDevAttrMultiProcessorCount, dev);
    int grid = occ * sms;
    if (grid > NITEMS) grid = NITEMS;
    if (grid < 1) grid = 1;

    mega_kernel<<<grid, 128, SMEM_BYTES>>>(mu, var, labels, out);
}